// round 6
// baseline (speedup 1.0000x reference)
#include <cuda_runtime.h>
#include <cuda_bf16.h>
#include <stdint.h>

#define OUT_CH 32
#define MAX_NODES 100000
#define MIN_BLOCKS 64

__device__ float g_Wt[MAX_NODES * OUT_CH];   // transposed W, L2-resident 12.8 MB
__device__ int   g_part[MIN_BLOCKS];         // per-block row minima (always fully written)

// ---------------------------------------------------------------------------
// K1 (fused prep): blocks [0, NB): transpose W[32,N]->Wt[N,32] and out[n,:]=b.
//                  blocks [NB, NB+64): row-min partials -> g_part (plain stores).
// ---------------------------------------------------------------------------
__global__ void prep_kernel(const float* __restrict__ W, const float* __restrict__ b,
                            const int* __restrict__ rows, float* __restrict__ out,
                            int N, int E, int NB) {
    if ((int)blockIdx.x < NB) {
        int n = blockIdx.x * blockDim.x + threadIdx.x;
        if (n >= N) return;
        float v[OUT_CH];
        #pragma unroll
        for (int c = 0; c < OUT_CH; c++)
            v[c] = __ldg(&W[(size_t)c * N + n]);
        float4* dst = reinterpret_cast<float4*>(&g_Wt[(size_t)n * OUT_CH]);
        #pragma unroll
        for (int j = 0; j < OUT_CH / 4; j++)
            dst[j] = make_float4(v[4*j+0], v[4*j+1], v[4*j+2], v[4*j+3]);
        float4* o = reinterpret_cast<float4*>(&out[(size_t)n * OUT_CH]);
        #pragma unroll
        for (int j = 0; j < OUT_CH / 4; j++)
            o[j] = __ldg(reinterpret_cast<const float4*>(b) + j);
    } else {
        __shared__ int s_wmin[8];
        int blk = blockIdx.x - NB;                    // 0..63
        int i = blk * blockDim.x + threadIdx.x;
        int stride = MIN_BLOCKS * blockDim.x;
        int m = 0x7fffffff;
        for (; i < E; i += stride)
            m = min(m, __ldg(&rows[i]));
        #pragma unroll
        for (int off = 16; off > 0; off >>= 1)
            m = min(m, __shfl_xor_sync(0xffffffffu, m, off));
        int w = threadIdx.x >> 5;
        if ((threadIdx.x & 31) == 0) s_wmin[w] = m;
        __syncthreads();
        if (threadIdx.x == 0) {
            int bm = s_wmin[0];
            #pragma unroll
            for (int k = 1; k < 8; k++) bm = min(bm, s_wmin[k]);
            g_part[blk] = bm;                         // plain store, no reset needed
        }
    }
}

// ---------------------------------------------------------------------------
// K2: scatter. 8 threads per edge-quad slot; each thread handles channel-quad t
// of FOUR independent edges -> 4 independent LDG->RED chains.
// ---------------------------------------------------------------------------
__global__ void scatter_kernel(const int* __restrict__ ei, int E, int N,
                               float* __restrict__ out) {
    // block-level rowmin reduction over the 64 partials
    __shared__ int s_min;
    if (threadIdx.x < 32) {
        int m = min(g_part[threadIdx.x], g_part[threadIdx.x + 32]);
        #pragma unroll
        for (int off = 16; off > 0; off >>= 1)
            m = min(m, __shfl_xor_sync(0xffffffffu, m, off));
        if (threadIdx.x == 0) s_min = m;
    }
    __syncthreads();
    int minr = s_min;

    int quarter = (E + 3) >> 2;
    long long gtid = (long long)blockIdx.x * blockDim.x + threadIdx.x;
    long long g = gtid >> 3;
    int t = (int)(gtid & 7);
    if (g >= quarter) return;

    int e0 = (int)g;
    int e1 = e0 + quarter;
    int e2 = e1 + quarter;
    int e3 = e2 + quarter;
    bool h1 = e1 < E, h2 = e2 < E, h3 = e3 < E;

    // front-load all index reads (independent)
    int row0 = __ldg(&ei[e0]);
    int col0 = __ldg(&ei[E + e0]);
    int row1 = h1 ? __ldg(&ei[e1]) : 0;
    int col1 = h1 ? __ldg(&ei[E + e1]) : 0;
    int row2 = h2 ? __ldg(&ei[e2]) : 0;
    int col2 = h2 ? __ldg(&ei[E + e2]) : 0;
    int row3 = h3 ? __ldg(&ei[e3]) : 0;
    int col3 = h3 ? __ldg(&ei[E + e3]) : 0;

    row0 -= minr; row1 -= minr; row2 -= minr; row3 -= minr;
    bool ok0 = (unsigned)row0 < (unsigned)N && (unsigned)col0 < (unsigned)N;
    bool ok1 = h1 && (unsigned)row1 < (unsigned)N && (unsigned)col1 < (unsigned)N;
    bool ok2 = h2 && (unsigned)row2 < (unsigned)N && (unsigned)col2 < (unsigned)N;
    bool ok3 = h3 && (unsigned)row3 < (unsigned)N && (unsigned)col3 < (unsigned)N;

    // independent gathers (all in flight together)
    float4 v0, v1, v2, v3;
    if (ok0) v0 = __ldg(reinterpret_cast<const float4*>(&g_Wt[(size_t)col0 * OUT_CH]) + t);
    if (ok1) v1 = __ldg(reinterpret_cast<const float4*>(&g_Wt[(size_t)col1 * OUT_CH]) + t);
    if (ok2) v2 = __ldg(reinterpret_cast<const float4*>(&g_Wt[(size_t)col2 * OUT_CH]) + t);
    if (ok3) v3 = __ldg(reinterpret_cast<const float4*>(&g_Wt[(size_t)col3 * OUT_CH]) + t);

    if (ok0) {
        float* dst = &out[(size_t)row0 * OUT_CH + t * 4];
        asm volatile("red.global.add.v4.f32 [%0], {%1, %2, %3, %4};"
                     :: "l"(dst), "f"(v0.x), "f"(v0.y), "f"(v0.z), "f"(v0.w) : "memory");
    }
    if (ok1) {
        float* dst = &out[(size_t)row1 * OUT_CH + t * 4];
        asm volatile("red.global.add.v4.f32 [%0], {%1, %2, %3, %4};"
                     :: "l"(dst), "f"(v1.x), "f"(v1.y), "f"(v1.z), "f"(v1.w) : "memory");
    }
    if (ok2) {
        float* dst = &out[(size_t)row2 * OUT_CH + t * 4];
        asm volatile("red.global.add.v4.f32 [%0], {%1, %2, %3, %4};"
                     :: "l"(dst), "f"(v2.x), "f"(v2.y), "f"(v2.z), "f"(v2.w) : "memory");
    }
    if (ok3) {
        float* dst = &out[(size_t)row3 * OUT_CH + t * 4];
        asm volatile("red.global.add.v4.f32 [%0], {%1, %2, %3, %4};"
                     :: "l"(dst), "f"(v3.x), "f"(v3.y), "f"(v3.z), "f"(v3.w) : "memory");
    }
}

// ---------------------------------------------------------------------------
extern "C" void kernel_launch(void* const* d_in, const int* in_sizes, int n_in,
                              void* d_out, int out_size) {
    const int*   ei = (const int*)d_in[0];     // [2, E]
    const float* W  = (const float*)d_in[1];   // [32, N]
    const float* b  = (const float*)d_in[2];   // [32]
    float* out = (float*)d_out;                // [N, 32]

    int E = in_sizes[0] / 2;
    int N = in_sizes[1] / OUT_CH;

    int threads = 256;
    int NB = (N + threads - 1) / threads;
    prep_kernel<<<NB + MIN_BLOCKS, threads>>>(W, b, ei, out, N, E, NB);

    long long quarter = (E + 3) >> 2;
    long long work = quarter * 8;
    int blocks = (int)((work + threads - 1) / threads);
    scatter_kernel<<<blocks, threads>>>(ei, E, N, out);
}